// round 16
// baseline (speedup 1.0000x reference)
#include <cuda_runtime.h>
#include <cuda_fp16.h>
#include <cstdint>

// ---------------------------------------------------------------------------
// FusedQKVLinear: out[8192, 6144] = x[8192,4096] @ W^T, W dequantized from
// 4-bit codebook codes + per-128-group scales.
// fp16 operands (11-bit mantissa == tf32) + fp32 accumulate:
//   1) xround_kernel : x -> fp16(rne) into g_X
//   2) dequant_kernel x3 : W = fp16(cb[code]*scale) into g_W
//   3) qkv_gemm : 128x128x64 CTA tile, 256 thr (8 warps, 64x32 warp tile),
//      3-stage cp.async, 2 CTAs/SM (decoupled sync domains),
//      mma.sync.m16n8k16.f16.f32.
// ---------------------------------------------------------------------------

#define D_K     4096
#define T_M     8192
#define O_N     6144

__device__ __half g_W[(size_t)O_N * D_K];   // fp16 dequantized weights [O, D]
__device__ __half g_X[(size_t)T_M * D_K];   // fp16 activations [T, D]

__device__ __forceinline__ uint32_t smem_u32(const void* p) {
    uint32_t a;
    asm("{ .reg .u64 t; cvta.to.shared.u64 t, %1; cvt.u32.u64 %0, t; }" : "=r"(a) : "l"(p));
    return a;
}

// ---------------- pre-pass kernels ----------------

#define XR_HALF (T_M * D_K / 8)   // half of the float4 count

__global__ void __launch_bounds__(256) xround_kernel(const float* __restrict__ x) {
    size_t i = (size_t)blockIdx.x * blockDim.x + threadIdx.x;  // float4 index
#pragma unroll
    for (int r = 0; r < 2; r++) {
        size_t j = i + (size_t)r * XR_HALF;
        float4 v = ((const float4*)x)[j];
        __half2 h01 = __floats2half2_rn(v.x, v.y);
        __half2 h23 = __floats2half2_rn(v.z, v.w);
        uint2 o;
        o.x = *reinterpret_cast<uint32_t*>(&h01);
        o.y = *reinterpret_cast<uint32_t*>(&h23);
        ((uint2*)g_X)[j] = o;
    }
}

__global__ void __launch_bounds__(256) dequant_kernel(const int* __restrict__ codes,
                                                      const float* __restrict__ scales,
                                                      const float* __restrict__ cbp,
                                                      size_t out_off, size_t half_vec4) {
    __shared__ float cb[16];
    if (threadIdx.x < 16) cb[threadIdx.x] = cbp[threadIdx.x];
    __syncthreads();
    size_t i0 = (size_t)blockIdx.x * blockDim.x + threadIdx.x;  // vec4 index
#pragma unroll
    for (int r = 0; r < 2; r++) {
        size_t i = i0 + (size_t)r * half_vec4;
        int4 c = ((const int4*)codes)[i];
        size_t base = i * 4;
        size_t o = base >> 12;           // row (within this weight)
        int g = (int)((base >> 7) & 31); // 128-group within row
        float s = __ldg(&scales[o * 32 + g]);
        __half2 h01 = __floats2half2_rn(cb[c.x] * s, cb[c.y] * s);
        __half2 h23 = __floats2half2_rn(cb[c.z] * s, cb[c.w] * s);
        uint2 rr;
        rr.x = *reinterpret_cast<uint32_t*>(&h01);
        rr.y = *reinterpret_cast<uint32_t*>(&h23);
        ((uint2*)(g_W + out_off))[i] = rr;
    }
}

// ---------------- GEMM ----------------

#define BM 128
#define BN 128
#define BK 64                            // halfs per k-iter (128 bytes/row)
#define NTHREADS 256
#define STAGES 3
#define PADK 72                          // halfs per smem row (144B, conflict-free)
#define A_HALFS (BM * PADK)              // 9216
#define B_HALFS (BN * PADK)              // 9216
#define STAGE_HALFS (A_HALFS + B_HALFS)              // 18432
#define SMEM_BYTES (STAGES * STAGE_HALFS * 2)        // 110592 -> 2 CTAs/SM
#define K_ITERS (D_K / BK)               // 64
#define GROUP_M 8
#define N_TILES (O_N / BN)               // 48
#define M_TILES (T_M / BM)               // 64

__device__ __forceinline__ void cp16(uint32_t dst, const void* src) {
    asm volatile("cp.async.cg.shared.global [%0], [%1], 16;" :: "r"(dst), "l"(src) : "memory");
}

__device__ __forceinline__ void mma_f16(float& d0, float& d1, float& d2, float& d3,
                                        uint32_t a0, uint32_t a1, uint32_t a2, uint32_t a3,
                                        uint32_t b0, uint32_t b1) {
    asm volatile(
        "mma.sync.aligned.m16n8k16.row.col.f32.f16.f16.f32 "
        "{%0,%1,%2,%3}, {%4,%5,%6,%7}, {%8,%9}, {%0,%1,%2,%3};"
        : "+f"(d0), "+f"(d1), "+f"(d2), "+f"(d3)
        : "r"(a0), "r"(a1), "r"(a2), "r"(a3), "r"(b0), "r"(b1));
}

__global__ void __launch_bounds__(NTHREADS, 2) qkv_gemm(float* __restrict__ out) {
    extern __shared__ __align__(128) __half smem[];
    const uint32_t sbase = smem_u32(smem);
    const int tid = threadIdx.x;

    // grid swizzle: groups of GROUP_M m-tiles sweep all n-tiles (L2 reuse)
    int bid = blockIdx.x;
    const int per_group = GROUP_M * N_TILES;
    int grp = bid / per_group;
    int rem = bid % per_group;
    int m_idx = grp * GROUP_M + (rem % GROUP_M);
    int n_idx = rem / GROUP_M;
    const int m0 = m_idx * BM;
    const int n0 = n_idx * BN;

    const __half* Ag = g_X + (size_t)m0 * D_K;
    const __half* Bg = g_W + (size_t)n0 * D_K;

    // one stage: A 1024 + B 1024 16B chunks, 8 per thread (256 threads)
    auto issue_stage = [&](int L, int s) {
        const __half* ga = Ag + L * BK;
        const __half* gb = Bg + L * BK;
        uint32_t sa = sbase + (uint32_t)(s * STAGE_HALFS) * 2u;
        uint32_t sb = sa + (uint32_t)A_HALFS * 2u;
#pragma unroll
        for (int i = 0; i < 4; i++) {
            int chunk = tid + i * NTHREADS;      // 0..1023
            int row = chunk >> 3;
            int cc  = chunk & 7;                 // 16B chunk = 8 halfs
            uint32_t soff = (uint32_t)(row * PADK + cc * 8) * 2u;
            cp16(sa + soff, ga + (size_t)row * D_K + cc * 8);
        }
#pragma unroll
        for (int i = 0; i < 4; i++) {
            int chunk = tid + i * NTHREADS;      // 0..1023
            int row = chunk >> 3;
            int cc  = chunk & 7;
            uint32_t soff = (uint32_t)(row * PADK + cc * 8) * 2u;
            cp16(sb + soff, gb + (size_t)row * D_K + cc * 8);
        }
        asm volatile("cp.async.commit_group;" ::: "memory");
    };

    // warp layout: 2 (M) x 4 (N); warp tile 64x32
    const int w = tid >> 5, lane = tid & 31;
    const int wm = w & 1, wn = w >> 1;
    const int lg = lane >> 2;   // fragment row group 0..7
    const int lc = lane & 3;    // fragment col group 0..3

    float acc[4][4][4];
#pragma unroll
    for (int i = 0; i < 4; i++)
#pragma unroll
        for (int j = 0; j < 4; j++)
#pragma unroll
            for (int q = 0; q < 4; q++) acc[i][j][q] = 0.f;

    // prologue: stages 0..STAGES-2
#pragma unroll
    for (int L = 0; L < STAGES - 1; L++) issue_stage(L, L);

    for (int it = 0; it < K_ITERS; it++) {
        asm volatile("cp.async.wait_group %0;" :: "n"(STAGES - 2) : "memory");
        __syncthreads();   // stage `it` ready for all; oldest slot free for all

        int Ln = it + STAGES - 1;
        if (Ln < K_ITERS) issue_stage(Ln, Ln % STAGES);
        else asm volatile("cp.async.commit_group;" ::: "memory");

        const __half* sA = smem + (it % STAGES) * STAGE_HALFS;
        const __half* sB = sA + A_HALFS;

#pragma unroll
        for (int ks = 0; ks < 4; ks++) {   // 4 x k16 within BK=64
            const int k0 = ks * 16 + 2 * lc;   // half index (even -> 4B aligned)
            uint32_t a[4][4];
#pragma unroll
            for (int mt = 0; mt < 4; mt++) {
                int r0 = wm * 64 + mt * 16 + lg;
                a[mt][0] = *(const uint32_t*)&sA[r0 * PADK + k0];
                a[mt][1] = *(const uint32_t*)&sA[(r0 + 8) * PADK + k0];
                a[mt][2] = *(const uint32_t*)&sA[r0 * PADK + k0 + 8];
                a[mt][3] = *(const uint32_t*)&sA[(r0 + 8) * PADK + k0 + 8];
            }
            uint32_t b[4][2];
#pragma unroll
            for (int nt = 0; nt < 4; nt++) {
                int n = wn * 32 + nt * 8 + lg;
                b[nt][0] = *(const uint32_t*)&sB[n * PADK + k0];
                b[nt][1] = *(const uint32_t*)&sB[n * PADK + k0 + 8];
            }
#pragma unroll
            for (int mt = 0; mt < 4; mt++)
#pragma unroll
                for (int nt = 0; nt < 4; nt++)
                    mma_f16(acc[mt][nt][0], acc[mt][nt][1], acc[mt][nt][2], acc[mt][nt][3],
                            a[mt][0], a[mt][1], a[mt][2], a[mt][3],
                            b[nt][0], b[nt][1]);
        }
    }

    // epilogue: segmented q/k/v output (BN=128 divides all segment boundaries)
    size_t seg_off; int ldw, nloc;
    if (n0 < 4096)      { seg_off = 0;                  ldw = 4096; nloc = n0; }
    else if (n0 < 5120) { seg_off = (size_t)T_M * 4096; ldw = 1024; nloc = n0 - 4096; }
    else                { seg_off = (size_t)T_M * 5120; ldw = 1024; nloc = n0 - 5120; }

#pragma unroll
    for (int mt = 0; mt < 4; mt++) {
        int row = m0 + wm * 64 + mt * 16 + lg;
#pragma unroll
        for (int nt = 0; nt < 4; nt++) {
            int col = nloc + wn * 32 + nt * 8 + lc * 2;
            float2 v0 = make_float2(acc[mt][nt][0], acc[mt][nt][1]);
            float2 v1 = make_float2(acc[mt][nt][2], acc[mt][nt][3]);
            *(float2*)(out + seg_off + (size_t)row * ldw + col) = v0;
            *(float2*)(out + seg_off + (size_t)(row + 8) * ldw + col) = v1;
        }
    }
}

// ---------------- launch ----------------

extern "C" void kernel_launch(void* const* d_in, const int* in_sizes, int n_in,
                              void* d_out, int out_size) {
    const float* x  = (const float*)d_in[0];
    const int*   qc = (const int*)  d_in[1];
    const float* qs = (const float*)d_in[2];
    const float* qb = (const float*)d_in[3];
    const int*   kc = (const int*)  d_in[4];
    const float* ks = (const float*)d_in[5];
    const float* kb = (const float*)d_in[6];
    const int*   vc = (const int*)  d_in[7];
    const float* vs = (const float*)d_in[8];
    const float* vb = (const float*)d_in[9];
    float* out = (float*)d_out;
    (void)in_sizes; (void)n_in; (void)out_size;

    xround_kernel<<<16384, 256>>>(x);
    dequant_kernel<<<8192, 256>>>(qc, qs, qb, 0,                   (size_t)2097152);
    dequant_kernel<<<2048, 256>>>(kc, ks, kb, (size_t)4096 * 4096, (size_t)524288);
    dequant_kernel<<<2048, 256>>>(vc, vs, vb, (size_t)5120 * 4096, (size_t)524288);

    cudaFuncSetAttribute(qkv_gemm, cudaFuncAttributeMaxDynamicSharedMemorySize, SMEM_BYTES);
    qkv_gemm<<<M_TILES * N_TILES, NTHREADS, SMEM_BYTES>>>(out);
}

// round 17
// speedup vs baseline: 1.0097x; 1.0097x over previous
#include <cuda_runtime.h>
#include <cuda_fp16.h>
#include <cstdint>

// ---------------------------------------------------------------------------
// FusedQKVLinear: out[8192, 6144] = x[8192,4096] @ W^T, W dequantized from
// 4-bit codebook codes + per-128-group scales.
// fp16 operands (11-bit mantissa == tf32) + fp32 accumulate:
//   1) xround_kernel : x -> fp16(rne) into g_X           (MLP=4)
//   2) dequant_all : one launch for q/k/v weights        (MLP=4)
//   3) qkv_gemm : 128x256x128 CTA tile, 256 thr (8 warps, 64x64 warp tile),
//      2-stage cp.async (BK=128 -> 32 iters), scalar LDS fragments,
//      mma.sync.m16n8k16.f16.f32.   [R15 config, frozen]
// ---------------------------------------------------------------------------

#define D_K     4096
#define T_M     8192
#define O_N     6144

__device__ __half g_W[(size_t)O_N * D_K];   // fp16 dequantized weights [O, D]
__device__ __half g_X[(size_t)T_M * D_K];   // fp16 activations [T, D]

__device__ __forceinline__ uint32_t smem_u32(const void* p) {
    uint32_t a;
    asm("{ .reg .u64 t; cvta.to.shared.u64 t, %1; cvt.u32.u64 %0, t; }" : "=r"(a) : "l"(p));
    return a;
}

// ---------------- pre-pass kernels ----------------

#define XR_Q ((size_t)T_M * D_K / 16)   // quarter of the float4 count = 2,097,152

__global__ void __launch_bounds__(256) xround_kernel(const float* __restrict__ x) {
    size_t i = (size_t)blockIdx.x * blockDim.x + threadIdx.x;  // float4 index
    float4 v[4];
#pragma unroll
    for (int r = 0; r < 4; r++) v[r] = ((const float4*)x)[i + (size_t)r * XR_Q];
#pragma unroll
    for (int r = 0; r < 4; r++) {
        __half2 h01 = __floats2half2_rn(v[r].x, v[r].y);
        __half2 h23 = __floats2half2_rn(v[r].z, v[r].w);
        uint2 o;
        o.x = *reinterpret_cast<uint32_t*>(&h01);
        o.y = *reinterpret_cast<uint32_t*>(&h23);
        ((uint2*)g_X)[i + (size_t)r * XR_Q] = o;
    }
}

// one launch for all of q/k/v. Virtual weight rows: q [0,4096), k [4096,5120),
// v [5120,6144). vec4 index space: q [0, 4194304), k [.., 5242880), v [.., 6291456).
#define DQ_Q ((size_t)1572864)   // quarter of total vec4 chunks

__global__ void __launch_bounds__(256) dequant_all(
        const int* __restrict__ qc, const float* __restrict__ qs, const float* __restrict__ qcb,
        const int* __restrict__ kc, const float* __restrict__ ksc, const float* __restrict__ kcb,
        const int* __restrict__ vc, const float* __restrict__ vsc, const float* __restrict__ vcb) {
    __shared__ float cb[3][16];
    if (threadIdx.x < 16) {
        cb[0][threadIdx.x] = qcb[threadIdx.x];
        cb[1][threadIdx.x] = kcb[threadIdx.x];
        cb[2][threadIdx.x] = vcb[threadIdx.x];
    }
    __syncthreads();
    size_t i0 = (size_t)blockIdx.x * blockDim.x + threadIdx.x;  // vec4 index

    int4  c[4];
    float s[4];
    int   seg[4];
#pragma unroll
    for (int r = 0; r < 4; r++) {
        size_t i = i0 + (size_t)r * DQ_Q;
        size_t o = i >> 10;                 // virtual row (4096 halfs/row, 1024 vec4/row)
        int g = (int)((i >> 5) & 31);       // 128-group within row
        const int* cp; const float* sp; size_t li, lo;
        if (o < 4096)      { seg[r] = 0; cp = qc;  sp = qs;  li = i;            lo = o; }
        else if (o < 5120) { seg[r] = 1; cp = kc;  sp = ksc; li = i - 4194304;  lo = o - 4096; }
        else               { seg[r] = 2; cp = vc;  sp = vsc; li = i - 5242880;  lo = o - 5120; }
        c[r] = ((const int4*)cp)[li];
        s[r] = __ldg(&sp[lo * 32 + g]);
    }
#pragma unroll
    for (int r = 0; r < 4; r++) {
        size_t i = i0 + (size_t)r * DQ_Q;
        const float* cbs = cb[seg[r]];
        __half2 h01 = __floats2half2_rn(cbs[c[r].x] * s[r], cbs[c[r].y] * s[r]);
        __half2 h23 = __floats2half2_rn(cbs[c[r].z] * s[r], cbs[c[r].w] * s[r]);
        uint2 rr;
        rr.x = *reinterpret_cast<uint32_t*>(&h01);
        rr.y = *reinterpret_cast<uint32_t*>(&h23);
        ((uint2*)g_W)[i] = rr;
    }
}

// ---------------- GEMM (R15 config, frozen) ----------------

#define BM 128
#define BN 256
#define BK 128                           // halfs per k-iter (256 bytes/row)
#define NTHREADS 256
#define STAGES 2
#define PADK 136                         // halfs per smem row (272B, conflict-free)
#define A_HALFS (BM * PADK)              // 17408
#define B_HALFS (BN * PADK)              // 34816
#define STAGE_HALFS (A_HALFS + B_HALFS)              // 52224
#define SMEM_BYTES (STAGES * STAGE_HALFS * 2)        // 208896
#define K_ITERS (D_K / BK)               // 32
#define CHUNKS_PER_ROW (BK / 8)          // 16 (16B chunks)
#define GROUP_M 8
#define N_TILES (O_N / BN)               // 24
#define M_TILES (T_M / BM)               // 64

__device__ __forceinline__ void cp16(uint32_t dst, const void* src) {
    asm volatile("cp.async.cg.shared.global [%0], [%1], 16;" :: "r"(dst), "l"(src) : "memory");
}

__device__ __forceinline__ void mma_f16(float& d0, float& d1, float& d2, float& d3,
                                        uint32_t a0, uint32_t a1, uint32_t a2, uint32_t a3,
                                        uint32_t b0, uint32_t b1) {
    asm volatile(
        "mma.sync.aligned.m16n8k16.row.col.f32.f16.f16.f32 "
        "{%0,%1,%2,%3}, {%4,%5,%6,%7}, {%8,%9}, {%0,%1,%2,%3};"
        : "+f"(d0), "+f"(d1), "+f"(d2), "+f"(d3)
        : "r"(a0), "r"(a1), "r"(a2), "r"(a3), "r"(b0), "r"(b1));
}

__global__ void __launch_bounds__(NTHREADS, 1) qkv_gemm(float* __restrict__ out) {
    extern __shared__ __align__(128) __half smem[];
    const uint32_t sbase = smem_u32(smem);
    const int tid = threadIdx.x;

    // grid swizzle: groups of GROUP_M m-tiles sweep all n-tiles (L2 reuse)
    int bid = blockIdx.x;
    const int per_group = GROUP_M * N_TILES;
    int grp = bid / per_group;
    int rem = bid % per_group;
    int m_idx = grp * GROUP_M + (rem % GROUP_M);
    int n_idx = rem / GROUP_M;
    const int m0 = m_idx * BM;
    const int n0 = n_idx * BN;

    const __half* Ag = g_X + (size_t)m0 * D_K;
    const __half* Bg = g_W + (size_t)n0 * D_K;

    // one stage: A 2048 + B 4096 16B chunks, 24 per thread (256 threads)
    auto issue_stage = [&](int L, int s) {
        const __half* ga = Ag + L * BK;
        const __half* gb = Bg + L * BK;
        uint32_t sa = sbase + (uint32_t)(s * STAGE_HALFS) * 2u;
        uint32_t sb = sa + (uint32_t)A_HALFS * 2u;
#pragma unroll
        for (int i = 0; i < 8; i++) {
            int chunk = tid + i * NTHREADS;          // 0..2047
            int row = chunk / CHUNKS_PER_ROW;
            int cc  = chunk % CHUNKS_PER_ROW;
            uint32_t soff = (uint32_t)(row * PADK + cc * 8) * 2u;
            cp16(sa + soff, ga + (size_t)row * D_K + cc * 8);
        }
#pragma unroll
        for (int i = 0; i < 16; i++) {
            int chunk = tid + i * NTHREADS;          // 0..4095
            int row = chunk / CHUNKS_PER_ROW;
            int cc  = chunk % CHUNKS_PER_ROW;
            uint32_t soff = (uint32_t)(row * PADK + cc * 8) * 2u;
            cp16(sb + soff, gb + (size_t)row * D_K + cc * 8);
        }
        asm volatile("cp.async.commit_group;" ::: "memory");
    };

    // warp layout: 2 (M) x 4 (N); warp tile 64x64
    const int w = tid >> 5, lane = tid & 31;
    const int wm = w & 1, wn = w >> 1;
    const int lg = lane >> 2;   // fragment row group 0..7
    const int lc = lane & 3;    // fragment col group 0..3

    float acc[4][8][4];
#pragma unroll
    for (int i = 0; i < 4; i++)
#pragma unroll
        for (int j = 0; j < 8; j++)
#pragma unroll
            for (int q = 0; q < 4; q++) acc[i][j][q] = 0.f;

    // prologue: stage 0
    issue_stage(0, 0);

    for (int it = 0; it < K_ITERS; it++) {
        asm volatile("cp.async.wait_group 0;" ::: "memory");   // stage `it` landed
        __syncthreads();

        if (it + 1 < K_ITERS) issue_stage(it + 1, (it + 1) & 1);

        const __half* sA = smem + (it & 1) * STAGE_HALFS;
        const __half* sB = sA + A_HALFS;

#pragma unroll
        for (int ks = 0; ks < 8; ks++) {   // 8 x k16 within BK=128
            const int k0 = ks * 16 + 2 * lc;   // half index (even -> 4B aligned)
            uint32_t a[4][4];
#pragma unroll
            for (int mt = 0; mt < 4; mt++) {
                int r0 = wm * 64 + mt * 16 + lg;
                a[mt][0] = *(const uint32_t*)&sA[r0 * PADK + k0];
                a[mt][1] = *(const uint32_t*)&sA[(r0 + 8) * PADK + k0];
                a[mt][2] = *(const uint32_t*)&sA[r0 * PADK + k0 + 8];
                a[mt][3] = *(const uint32_t*)&sA[(r0 + 8) * PADK + k0 + 8];
            }
            uint32_t b[8][2];
#pragma unroll
            for (int nt = 0; nt < 8; nt++) {
                int n = wn * 64 + nt * 8 + lg;
                b[nt][0] = *(const uint32_t*)&sB[n * PADK + k0];
                b[nt][1] = *(const uint32_t*)&sB[n * PADK + k0 + 8];
            }
#pragma unroll
            for (int mt = 0; mt < 4; mt++)
#pragma unroll
                for (int nt = 0; nt < 8; nt++)
                    mma_f16(acc[mt][nt][0], acc[mt][nt][1], acc[mt][nt][2], acc[mt][nt][3],
                            a[mt][0], a[mt][1], a[mt][2], a[mt][3],
                            b[nt][0], b[nt][1]);
        }
    }

    // epilogue: segmented q/k/v output (BN=256 divides all segment boundaries)
    size_t seg_off; int ldw, nloc;
    if (n0 < 4096)      { seg_off = 0;                  ldw = 4096; nloc = n0; }
    else if (n0 < 5120) { seg_off = (size_t)T_M * 4096; ldw = 1024; nloc = n0 - 4096; }
    else                { seg_off = (size_t)T_M * 5120; ldw = 1024; nloc = n0 - 5120; }

#pragma unroll
    for (int mt = 0; mt < 4; mt++) {
        int row = m0 + wm * 64 + mt * 16 + lg;
#pragma unroll
        for (int nt = 0; nt < 8; nt++) {
            int col = nloc + wn * 64 + nt * 8 + lc * 2;
            float2 v0 = make_float2(acc[mt][nt][0], acc[mt][nt][1]);
            float2 v1 = make_float2(acc[mt][nt][2], acc[mt][nt][3]);
            *(float2*)(out + seg_off + (size_t)row * ldw + col) = v0;
            *(float2*)(out + seg_off + (size_t)(row + 8) * ldw + col) = v1;
        }
    }
}

// ---------------- launch ----------------

extern "C" void kernel_launch(void* const* d_in, const int* in_sizes, int n_in,
                              void* d_out, int out_size) {
    const float* x  = (const float*)d_in[0];
    const int*   qc = (const int*)  d_in[1];
    const float* qs = (const float*)d_in[2];
    const float* qb = (const float*)d_in[3];
    const int*   kc = (const int*)  d_in[4];
    const float* ks = (const float*)d_in[5];
    const float* kb = (const float*)d_in[6];
    const int*   vc = (const int*)  d_in[7];
    const float* vs = (const float*)d_in[8];
    const float* vb = (const float*)d_in[9];
    float* out = (float*)d_out;
    (void)in_sizes; (void)n_in; (void)out_size;

    // x: 8,388,608 float4 / 4 per thread = 2,097,152 threads = 8192 blocks
    xround_kernel<<<8192, 256>>>(x);
    // weights: 6,291,456 vec4 / 4 per thread = 1,572,864 threads = 6144 blocks
    dequant_all<<<6144, 256>>>(qc, qs, qb, kc, ks, kb, vc, vs, vb);

    cudaFuncSetAttribute(qkv_gemm, cudaFuncAttributeMaxDynamicSharedMemorySize, SMEM_BYTES);
    qkv_gemm<<<M_TILES * N_TILES, NTHREADS, SMEM_BYTES>>>(out);
}